// round 3
// baseline (speedup 1.0000x reference)
#include <cuda_runtime.h>
#include <cuda_bf16.h>

// Problem constants
#define BATCH  4096
#define DIN    256
#define DOUT   256
#define NEXP   64

// Tiling
#define NTILE   128     // cols per block (2 blocks per expert)
#define MCHUNK  64      // rows per m-iteration
#define XSTRIDE 68      // padded stride for transposed x: bank=(4k+r)%32 conflict-free
#define NTHREADS 512

#define SW_FLOATS  (DIN * NTILE)     // 32768 -> 128KB
#define SX_FLOATS  (DIN * XSTRIDE)   // 17408 ->  68KB
#define SMEM_BYTES ((SW_FLOATS + SX_FLOATS) * 4)   // 200704 B

__device__ int g_cnt[NEXP];            // zero-initialized; gemm restores to 0
__device__ int g_done;                 // arrival counter, restored to 0
__device__ int g_rows[NEXP * BATCH];   // per-expert gather lists

// ---------------------------------------------------------------------------
// Kernel 1: one-hot -> expert index, scatter into per-expert lists
// ---------------------------------------------------------------------------
__global__ void build_kernel(const float* __restrict__ onehot) {
    int b = blockIdx.x * blockDim.x + threadIdx.x;
    if (b >= BATCH) return;
    const float4* row = (const float4*)(onehot + (size_t)b * NEXP);
    int sel = 0;
#pragma unroll
    for (int j = 0; j < NEXP / 4; j++) {
        float4 v = row[j];
        if (v.x > 0.5f) sel = 4 * j + 0;
        if (v.y > 0.5f) sel = 4 * j + 1;
        if (v.z > 0.5f) sel = 4 * j + 2;
        if (v.w > 0.5f) sel = 4 * j + 3;
    }
    int p = atomicAdd(&g_cnt[sel], 1);
    g_rows[sel * BATCH + p] = b;
}

// packed fp32x2 FMA: d.lo += a.lo*b.lo ; d.hi += a.hi*b.hi
__device__ __forceinline__ void ffma2(unsigned long long& d,
                                      unsigned long long a,
                                      unsigned long long b) {
    asm("fma.rn.f32x2 %0, %1, %2, %0;" : "+l"(d) : "l"(a), "l"(b));
}
__device__ __forceinline__ unsigned long long dupf(float v) {
    unsigned long long r;
    asm("mov.b64 %0, {%1, %1};" : "=l"(r) : "f"(v));
    return r;
}
__device__ __forceinline__ float lo32(unsigned long long a) {
    return __uint_as_float((unsigned int)(a & 0xffffffffull));
}
__device__ __forceinline__ float hi32(unsigned long long a) {
    return __uint_as_float((unsigned int)(a >> 32));
}

// ---------------------------------------------------------------------------
// GEMM: blockIdx.y = expert, blockIdx.x = 128-col tile. 512 threads.
// Thread tile: 8 rows (4 f32x2 row-pairs) x 2 contiguous cols.
//   tc = tid & 63  -> cols c0 = 2*tc
//   tr = tid >> 6  -> rows r0 = 8*tr   (warp spans one tr -> x loads broadcast)
// ---------------------------------------------------------------------------
__global__ void __launch_bounds__(NTHREADS, 1)
gemm_kernel(const float* __restrict__ x,
            const float* __restrict__ W,
            const float* __restrict__ Bw,
            float* __restrict__ out) {
    extern __shared__ float smem[];
    float* s_w = smem;               // [k][c]  k*128 + c
    float* s_x = smem + SW_FLOATS;   // [k][r]  k*68 + r

    const int e   = blockIdx.y;
    const int n0  = blockIdx.x * NTILE;
    const int tid = threadIdx.x;
    const int tc  = tid & 63;
    const int tr  = tid >> 6;
    const int c0  = 2 * tc;
    const int r0  = 8 * tr;

    // --- stage W tile: float4 -> float4, natural layout, conflict-free ---
    {
        const float* We = W + ((size_t)e << 16) + n0;
        const int kk = tid >> 5;          // 0..15
        const int oo = (tid & 31) << 2;   // 0..124 step 4
#pragma unroll
        for (int it = 0; it < 16; it++) {
            int k = kk + (it << 4);
            float4 v = *(const float4*)(We + ((size_t)k << 8) + oo);
            *(float4*)(s_w + k * NTILE + oo) = v;
        }
    }

    const int  cnt  = g_cnt[e];
    const int* rows = g_rows + e * BATCH;

    float2 bias = *(const float2*)(Bw + (e << 8) + n0 + c0);

    for (int m0 = 0; m0 < cnt; m0 += MCHUNK) {
        __syncthreads();   // s_w ready (first iter) / previous chunk done with s_x

        // --- stage x chunk transposed: s_x[k][r] = x[rows[m0+r]][k] ---
        {
            const int r  = tid & 63;
            const int kg = tid >> 6;   // 0..7
            const int gr = m0 + r;
            const float4* xp = (gr < cnt)
                ? (const float4*)(x + ((size_t)rows[gr] << 8)) : (const float4*)0;
#pragma unroll
            for (int it = 0; it < 8; it++) {
                int k4 = kg + (it << 3);
                float4 v = xp ? xp[k4] : make_float4(0.f, 0.f, 0.f, 0.f);
                int k = k4 << 2;
                s_x[(k + 0) * XSTRIDE + r] = v.x;   // bank (4k+r)%32: conflict-free
                s_x[(k + 1) * XSTRIDE + r] = v.y;
                s_x[(k + 2) * XSTRIDE + r] = v.z;
                s_x[(k + 3) * XSTRIDE + r] = v.w;
            }
        }
        __syncthreads();

        // --- register tile: 4 row-pairs x 2 cols, f32x2-packed along rows ---
        unsigned long long acc[4][2];
#pragma unroll
        for (int p = 0; p < 4; p++) { acc[p][0] = 0ull; acc[p][1] = 0ull; }

#pragma unroll 4
        for (int k = 0; k < DIN; k++) {
            ulonglong2 aA = *(const ulonglong2*)(s_x + k * XSTRIDE + r0);
            ulonglong2 aB = *(const ulonglong2*)(s_x + k * XSTRIDE + r0 + 4);
            float2 wv = *(const float2*)(s_w + k * NTILE + c0);
            unsigned long long b0 = dupf(wv.x);
            unsigned long long b1 = dupf(wv.y);
            ffma2(acc[0][0], aA.x, b0); ffma2(acc[0][1], aA.x, b1);
            ffma2(acc[1][0], aA.y, b0); ffma2(acc[1][1], aA.y, b1);
            ffma2(acc[2][0], aB.x, b0); ffma2(acc[2][1], aB.x, b1);
            ffma2(acc[3][0], aB.y, b0); ffma2(acc[3][1], aB.y, b1);
        }

        // --- epilogue: unpack pairs, add bias, float2 stores (coalesced) ---
#pragma unroll
        for (int p = 0; p < 4; p++) {
            int m = m0 + r0 + 2 * p;
            if (m < cnt) {
                float2 v;
                v.x = lo32(acc[p][0]) + bias.x;
                v.y = lo32(acc[p][1]) + bias.y;
                *(float2*)(out + ((size_t)rows[m] << 8) + n0 + c0) = v;
            }
            if (m + 1 < cnt) {
                float2 v;
                v.x = hi32(acc[p][0]) + bias.x;
                v.y = hi32(acc[p][1]) + bias.y;
                *(float2*)(out + ((size_t)rows[m + 1] << 8) + n0 + c0) = v;
            }
        }
    }

    // --- restore g_cnt / g_done to zero for the next graph replay ---
    __syncthreads();
    if (tid == 0) {
        __threadfence();
        int arrived = atomicAdd(&g_done, 1);
        if (arrived == (int)(gridDim.x * gridDim.y) - 1) {
#pragma unroll
            for (int i = 0; i < NEXP; i++) g_cnt[i] = 0;
            g_done = 0;
            __threadfence();
        }
    }
}

// ---------------------------------------------------------------------------
extern "C" void kernel_launch(void* const* d_in, const int* in_sizes, int n_in,
                              void* d_out, int out_size) {
    const float* x      = (const float*)d_in[0];
    const float* onehot = (const float*)d_in[1];
    const float* W      = (const float*)d_in[2];
    const float* Bw     = (const float*)d_in[3];
    float* out          = (float*)d_out;

    cudaFuncSetAttribute(gemm_kernel,
                         cudaFuncAttributeMaxDynamicSharedMemorySize,
                         SMEM_BYTES);

    build_kernel<<<BATCH / 256, 256>>>(onehot);
    gemm_kernel<<<dim3(DOUT / NTILE, NEXP), NTHREADS, SMEM_BYTES>>>(x, W, Bw, out);
}